// round 5
// baseline (speedup 1.0000x reference)
#include <cuda_runtime.h>
#include <cstdint>

#define U_NODES 100000
#define I_NODES 150000
#define N_NODES (U_NODES + I_NODES)
#define DIM     64
#define N_EDGES 1250000
#define TOTAL   (N_NODES * DIM)      // 16,000,000 floats
#define SLOTS   40                   // max active degree (Poisson(4) tail: ~1e-18)

// Device globals (no allocations allowed). Zero-initialized at module load.
__device__ float    g_A[TOTAL];                       // layer-2 output
__device__ float    g_B[TOTAL];                       // layer-1 output
__device__ int2     g_edge[(size_t)N_NODES * SLOTS];  // (col, val) per-row slots
__device__ unsigned g_fill[N_NODES];                  // per-row cursor == active count

// ---------------- edge bucketing ----------------
// g_fill is zero on entry: zero-init at load, re-zeroed by spmm<2> each replay.
__global__ void scatter_kernel(const int*   __restrict__ row,
                               const int*   __restrict__ col,
                               const float* __restrict__ adj,
                               const float* __restrict__ msk) {
    int e = blockIdx.x * blockDim.x + threadIdx.x;
    if (e >= N_EDGES) return;
    float v = adj[e] * msk[e];
    if (v == 0.f) return;                        // ~20% dropped
    int r = row[e];
    unsigned p = atomicAdd(&g_fill[r], 1u);
    if (p < SLOTS)
        g_edge[(size_t)r * SLOTS + p] = make_int2(col[e], __float_as_int(v));
}

// ---------------- fused SpMM layers ----------------
// 16 threads per row (two rows per warp); thread t owns float4 column t.
// MODE 0: gather embeds (ue/ie)  -> write g_B                      (layer 1)
// MODE 1: gather g_B             -> write g_A                      (layer 2)
// MODE 2: gather g_A             -> out=(emb+B+A+acc)/4, zero fill (layer 3)
template <int MODE>
__device__ __forceinline__ float4 gather(const float4* __restrict__ ue4,
                                         const float4* __restrict__ ie4,
                                         const float4* __restrict__ cur,
                                         int c, int t) {
    if (MODE == 0)
        return (c < U_NODES) ? ue4[(size_t)c * 16 + t]
                             : ie4[(size_t)(c - U_NODES) * 16 + t];
    return cur[(size_t)c * 16 + t];
}

template <int MODE>
__global__ void __launch_bounds__(256, 6)
spmm_kernel(const float* __restrict__ ue,
            const float* __restrict__ ie,
            float* __restrict__ out) {
    int gid  = blockIdx.x * blockDim.x + threadIdx.x;
    int r    = gid >> 4;
    int t    = gid & 15;
    if (r >= N_NODES) return;
    unsigned lane = threadIdx.x & 31;
    unsigned base = lane & 16;            // start lane of my half-warp

    const int2* ep = g_edge + (size_t)r * SLOTS;
    const float4* ue4 = reinterpret_cast<const float4*>(ue);
    const float4* ie4 = reinterpret_cast<const float4*>(ie);
    const float4* cur = reinterpret_cast<const float4*>(MODE == 1 ? g_B : g_A);

    unsigned cnt = g_fill[r];
    if (cnt > SLOTS) cnt = SLOTS;

    // One coalesced meta load per thread: slot t of my row (128B per row total).
    int2 my = ep[t];
    int   mcol = my.x;
    float mval = __int_as_float(my.y);

    unsigned n16  = (cnt < 16u) ? cnt : 16u;
    // Both half-warps must run the same shfl trip count (full-mask shfl).
    unsigned nmax = n16;
    unsigned other = __shfl_xor_sync(0xffffffffu, n16, 16);
    if (other > nmax) nmax = other;

    float4 acc0 = make_float4(0.f, 0.f, 0.f, 0.f);
    float4 acc1 = acc0;

    for (unsigned e = 0; e < nmax; e += 4) {
        // e in {0,4,8,12}; source lanes base+e+k <= base+15: stays in my half.
        int   c0 = __shfl_sync(0xffffffffu, mcol, base + e + 0);
        int   c1 = __shfl_sync(0xffffffffu, mcol, base + e + 1);
        int   c2 = __shfl_sync(0xffffffffu, mcol, base + e + 2);
        int   c3 = __shfl_sync(0xffffffffu, mcol, base + e + 3);
        float v0 = __shfl_sync(0xffffffffu, mval, base + e + 0);
        float v1 = __shfl_sync(0xffffffffu, mval, base + e + 1);
        float v2 = __shfl_sync(0xffffffffu, mval, base + e + 2);
        float v3 = __shfl_sync(0xffffffffu, mval, base + e + 3);

        float4 x0, x1, x2, x3;
        bool p0 = (e + 0) < n16, p1 = (e + 1) < n16;
        bool p2 = (e + 2) < n16, p3 = (e + 3) < n16;
        if (p0) x0 = gather<MODE>(ue4, ie4, cur, c0, t);
        if (p1) x1 = gather<MODE>(ue4, ie4, cur, c1, t);
        if (p2) x2 = gather<MODE>(ue4, ie4, cur, c2, t);
        if (p3) x3 = gather<MODE>(ue4, ie4, cur, c3, t);

        if (p0) { acc0.x += v0*x0.x; acc0.y += v0*x0.y; acc0.z += v0*x0.z; acc0.w += v0*x0.w; }
        if (p1) { acc1.x += v1*x1.x; acc1.y += v1*x1.y; acc1.z += v1*x1.z; acc1.w += v1*x1.w; }
        if (p2) { acc0.x += v2*x2.x; acc0.y += v2*x2.y; acc0.z += v2*x2.z; acc0.w += v2*x2.w; }
        if (p3) { acc1.x += v3*x3.x; acc1.y += v3*x3.y; acc1.z += v3*x3.z; acc1.w += v3*x3.w; }
    }

    // Rare tail (cnt > 16): direct loads, no shfl (divergence-safe).
    for (unsigned e = 16; e < cnt; ++e) {
        int2 m = ep[e];
        float w = __int_as_float(m.y);
        float4 y = gather<MODE>(ue4, ie4, cur, m.x, t);
        acc0.x += w*y.x; acc0.y += w*y.y; acc0.z += w*y.z; acc0.w += w*y.w;
    }

    float4 acc;
    acc.x = acc0.x + acc1.x; acc.y = acc0.y + acc1.y;
    acc.z = acc0.z + acc1.z; acc.w = acc0.w + acc1.w;

    size_t idx = (size_t)r * 16 + t;
    if (MODE == 0) {
        reinterpret_cast<float4*>(g_B)[idx] = acc;
    } else if (MODE == 1) {
        reinterpret_cast<float4*>(g_A)[idx] = acc;
    } else {
        float4 em = (r < U_NODES) ? ue4[idx] : ie4[(size_t)(r - U_NODES) * 16 + t];
        float4 bb = reinterpret_cast<const float4*>(g_B)[idx];
        float4 aa = reinterpret_cast<const float4*>(g_A)[idx];
        float4 o;
        o.x = (em.x + bb.x + aa.x + acc.x) * 0.25f;
        o.y = (em.y + bb.y + aa.y + acc.y) * 0.25f;
        o.z = (em.z + bb.z + aa.z + acc.z) * 0.25f;
        o.w = (em.w + bb.w + aa.w + acc.w) * 0.25f;
        reinterpret_cast<float4*>(out)[idx] = o;
        if (t == 0) g_fill[r] = 0;               // reset cursor for next replay
    }
}

extern "C" void kernel_launch(void* const* d_in, const int* in_sizes, int n_in,
                              void* d_out, int out_size) {
    const int*   row = (const int*)  d_in[0];
    const int*   col = (const int*)  d_in[1];
    const float* adj = (const float*)d_in[2];
    const float* msk = (const float*)d_in[3];
    const float* ue  = (const float*)d_in[4];
    const float* ie  = (const float*)d_in[5];
    float* out = (float*)d_out;

    const int NT = 256;
    const int gridEdge = (N_EDGES + NT - 1) / NT;
    const int gridRow  = (N_NODES * 16 + NT - 1) / NT;   // 15625

    scatter_kernel<<<gridEdge, NT>>>(row, col, adj, msk);
    spmm_kernel<0><<<gridRow, NT>>>(ue, ie, out);
    spmm_kernel<1><<<gridRow, NT>>>(ue, ie, out);
    spmm_kernel<2><<<gridRow, NT>>>(ue, ie, out);
}